// round 15
// baseline (speedup 1.0000x reference)
#include <cuda_runtime.h>
#include <cuda_bf16.h>

// TrafficAugmentation [B=2048, S=4096] -> [B, S, 1] f32.
//
// Two kernels:
//  K1 (P1): lean per-position delay countdown (branchless paired walks,
//      aligned LDS.128, deferred crossing resolve) -> g_snxt (u16).
//      Only dly staged in SMEM (16.4KB).
//  K2 (P2-P7): stages ONLY snxt (8KB) + exit table (8KB) in one pool;
//      x read straight from gmem in P4 (exact-order float4 __ldg sums).
//      After P4 the pool (16KB) aliases the f32 outrow. ~16.6KB smem
//      -> ~8 blocks/SM.

#define SS     4096
#define CHUNK  32
#define NCHUNK (SS / CHUNK)     // 128
#define MSSF   1448.0f
#define KILL16 0x8000u
#define NT     256
#define BMAX   2048

__device__ unsigned short g_snxt[(size_t)BMAX * SS];   // 16MB scratch

// Exact index-ordered sum of x[s0..e1) via aligned float4 gmem loads;
// fp op order identical to the scalar loop (predicated edges).
__device__ __forceinline__ float burst_sum_g(const float4* __restrict__ xv4,
                                             int s0, int e1)
{
    float buf = 0.0f;
    for (int jb = (s0 & ~3); jb < e1; jb += 4) {
        float4 v = __ldg(xv4 + (jb >> 2));
        if (jb     >= s0)                 buf = __fadd_rn(buf, v.x);
        if (jb + 1 >= s0 && jb + 1 < e1)  buf = __fadd_rn(buf, v.y);
        if (jb + 2 >= s0 && jb + 2 < e1)  buf = __fadd_rn(buf, v.z);
        if (jb + 3 >= s0 && jb + 3 < e1)  buf = __fadd_rn(buf, v.w);
    }
    return buf;
}

// ======================= K1: burst-end computation =======================
__global__ __launch_bounds__(NT)
void p1_kernel(const float* __restrict__ x,
               const float* __restrict__ dly,
               const float* __restrict__ rtt)
{
    __shared__ __align__(16) float sd[SS + 4];   // dly row + 1e30 pads

    const int row  = blockIdx.x;
    const size_t base = (size_t)row * SS;
    const int tid = threadIdx.x;

    {
        const float4* d4 = (const float4*)(dly + base);
        float4* sd4w = (float4*)sd;
        #pragma unroll
        for (int i = tid; i < SS / 4; i += NT) sd4w[i] = d4[i];
        if (tid < 4) sd[SS + tid] = 1e30f;
    }
    __syncthreads();

    const float4* sd4 = (const float4*)sd;
    const int phase = tid & 3;                   // s mod 4, constant over k
    unsigned short* snr = g_snxt + base;

    #pragma unroll 1
    for (int k = 0; k < SS / NT; k += 2) {
        const int sA = tid + k * NT;
        const int sB = sA + NT;
        float rA = __ldg(rtt + base + sA);       // issue early (MLP)
        float rB = __ldg(rtt + base + sB);
        const bool aliveA = (__ldg(x + base + sA) > 0.0f);
        const bool aliveB = (__ldg(x + base + sB) > 0.0f);
        int jA = sA - phase, jB = sB - phase;    // aligned batch starts
        int doneA = !aliveA, doneB = !aliveB;

        // peel: first batch with masked prefix (fsub(r,0) == identity)
        {
            float4 va = sd4[jA >> 2];
            float4 vb = sd4[jB >> 2];
            float a0 = (phase == 0) ? va.x : 0.0f;
            float a1 = (phase <= 1) ? va.y : 0.0f;
            float a2 = (phase <= 2) ? va.z : 0.0f;
            float b0 = (phase == 0) ? vb.x : 0.0f;
            float b1 = (phase <= 1) ? vb.y : 0.0f;
            float b2 = (phase <= 2) ? vb.z : 0.0f;
            float A4 = __fsub_rn(__fsub_rn(__fsub_rn(
                           __fsub_rn(rA, a0), a1), a2), va.w);
            float B4 = __fsub_rn(__fsub_rn(__fsub_rn(
                           __fsub_rn(rB, b0), b1), b2), vb.w);
            const int frzA = doneA | (A4 <= 0.0f);
            const int frzB = doneB | (B4 <= 0.0f);
            jA = frzA ? jA : jA + 4;             // freeze at terminal batch
            jB = frzB ? jB : jB + 4;
            rA = frzA ? rA : A4;                 // freeze batch-entry r
            rB = frzB ? rB : B4;
            doneA = frzA;
            doneB = frzB;
        }

        // steady state: aligned, unmasked; frozen walks replay idempotently
        while (!(doneA & doneB)) {
            float4 va = sd4[jA >> 2];
            float4 vb = sd4[jB >> 2];
            float A4 = __fsub_rn(__fsub_rn(__fsub_rn(
                           __fsub_rn(rA, va.x), va.y), va.z), va.w);
            float B4 = __fsub_rn(__fsub_rn(__fsub_rn(
                           __fsub_rn(rB, vb.x), vb.y), vb.z), vb.w);
            const int frzA = doneA | (A4 <= 0.0f);
            const int frzB = doneB | (B4 <= 0.0f);
            jA = frzA ? jA : jA + 4;
            jB = frzB ? jB : jB + 4;
            rA = frzA ? rA : A4;
            rB = frzB ? rB : B4;
            doneA = frzA;
            doneB = frzB;
            // 1e30 pads at sd[SS..SS+3] force termination just past SS
        }

        // resolve crossing once per walk (bit-exact replay of terminal batch)
        {
            float4 va = sd4[jA >> 2];
            float d0 = (jA     >= sA) ? va.x : 0.0f;
            float d1 = (jA + 1 >= sA) ? va.y : 0.0f;
            float d2 = (jA + 2 >= sA) ? va.z : 0.0f;
            float A1 = __fsub_rn(rA, d0);
            float A2 = __fsub_rn(A1, d1);
            float A3 = __fsub_rn(A2, d2);
            int c = jA + 1 + (int)(A1 > 0.0f) + (int)(A2 > 0.0f)
                           + (int)(A3 > 0.0f);
            c = (c > sA + 1) ? c : sA + 1;       // r<=0 at start: consume 1
            c = (c < SS) ? c : SS;
            snr[sA] = aliveA ? (unsigned short)c : (unsigned short)KILL16;
        }
        {
            float4 vb = sd4[jB >> 2];
            float d0 = (jB     >= sB) ? vb.x : 0.0f;
            float d1 = (jB + 1 >= sB) ? vb.y : 0.0f;
            float d2 = (jB + 2 >= sB) ? vb.z : 0.0f;
            float B1 = __fsub_rn(rB, d0);
            float B2 = __fsub_rn(B1, d1);
            float B3 = __fsub_rn(B2, d2);
            int c = jB + 1 + (int)(B1 > 0.0f) + (int)(B2 > 0.0f)
                           + (int)(B3 > 0.0f);
            c = (c > sB + 1) ? c : sB + 1;
            c = (c < SS) ? c : SS;
            snr[sB] = aliveB ? (unsigned short)c : (unsigned short)KILL16;
        }
    }
}

// ======================= K2: chain walk + emission =======================
__global__ __launch_bounds__(NT)
void p2_kernel(const float* __restrict__ x,
               float* __restrict__ out)
{
    // spool: [0:SS) = snxt, [SS:2*SS) = exit table (both u16).
    // After P4 both are dead; the 16KB pool aliases the f32 outrow[SS].
    __shared__ __align__(16) unsigned short spool[2 * SS];
    __shared__ unsigned short senter[NCHUNK];    // chain entry per chunk
    __shared__ int swsum[NCHUNK / 32];           // per-warp count totals
    __shared__ int s_total;                      // grand output count

    const int row  = blockIdx.x;
    const size_t base = (size_t)row * SS;
    const int tid = threadIdx.x;
    const float4* xv4 = (const float4*)(x + base);

    unsigned short* ssnxt = spool;
    unsigned short* sexit = spool + SS;

    // ---- P0: stage snxt row ----------------------------------------------
    {
        const uint4* n4 = (const uint4*)(g_snxt + base);
        uint4* sn4 = (uint4*)ssnxt;
        #pragma unroll
        for (int i = tid; i < SS / 8; i += NT) sn4[i] = n4[i];
    }
    __syncthreads();

    // ---- P2: exit table via warp-shfl pointer doubling -------------------
    {
        const int wid  = tid >> 5;
        const int lane = tid & 31;
        for (int c = wid; c < NCHUNK; c += NT / 32) {  // 16 chunks per warp
            const int cbase = c * CHUNK;
            const int cend  = cbase + CHUNK;
            unsigned short w = ssnxt[cbase + lane];
            int E = (w & KILL16) ? SS : (int)w;        // kill -> chain dies
            #pragma unroll
            for (int step = 0; step < 5; step++) {     // 2^5 >= CHUNK
                int val = __shfl_sync(0xffffffffu, E, E & 31);
                E = (E < cend) ? val : E;              // E >= cbase always
            }
            sexit[cbase + lane] = (unsigned short)E;
        }
    }
    __syncthreads();

    // ---- P3: serial top walk (<= NCHUNK hops, branchy) -------------------
    if (tid == 0) {
        int pos = 0;
        #pragma unroll 4
        for (int c = 0; c < NCHUNK; c++) {
            senter[c] = (unsigned short)pos;
            if (pos < (c + 1) * CHUNK) pos = sexit[pos];
        }
    }
    __syncthreads();

    // ---- P4: per-chunk counts; x sums straight from gmem -----------------
    unsigned long long lburst[CHUNK];            // local mem, seq push/pop
    int cnt = 0, nb = 0;
    if (tid < NCHUNK) {
        const int end = (tid + 1) * CHUNK;
        int s = senter[tid];
        while (s < end) {
            unsigned short w = ssnxt[s];
            if (w & KILL16) break;
            const int e1 = (int)w;
            float buf = burst_sum_g(xv4, s, e1);      // exact index order
            int nf = (int)ceilf(__fdiv_rn(buf, MSSF)) - 1;
            if (nf < 0) nf = 0;
            float rem = __fsub_rn(buf, __fmul_rn((float)nf, MSSF));
            cnt += nf + (rem > 0.0f ? 1 : 0);
            lburst[nb++] = ((unsigned long long)__float_as_uint(rem) << 32)
                         | (unsigned int)nf;
            s = e1;
        }
    }
    __syncthreads();   // snxt + exit dead -> pool becomes outrow

    // ---- P5: warp-shfl exclusive scan of chunk counts --------------------
    int inc = cnt;
    if (tid < NCHUNK) {
        const int lane = tid & 31;
        #pragma unroll
        for (int d = 1; d < 32; d <<= 1) {
            int n = __shfl_up_sync(0xffffffffu, inc, d);
            if (lane >= d) inc += n;
        }
        if (lane == 31) swsum[tid >> 5] = inc;          // warp inclusive total
    }
    __syncthreads();

    // ---- P6: pure emission of cached bursts + grand total ----------------
    float* outrow = (float*)spool;
    if (tid < NCHUNK) {
        int o = inc - cnt;                              // exclusive within warp
        #pragma unroll
        for (int k = 0; k < NCHUNK / 32; k++)
            if (k < (tid >> 5)) o += swsum[k];
        for (int i = 0; i < nb; i++) {
            unsigned long long v = lburst[i];
            int nf    = (int)(unsigned int)(v & 0xFFFFFFFFu);
            float rem = __uint_as_float((unsigned int)(v >> 32));
            int lim = nf;
            if (o + lim > SS) lim = SS - o;             // truncation (may be <=0)
            for (int k = 0; k < lim; k++) outrow[o + k] = MSSF;
            if (rem > 0.0f && o + nf < SS) outrow[o + nf] = rem;
            o += nf + (rem > 0.0f ? 1 : 0);             // slots [o,o+cnt) dense
        }
    } else if (tid == NCHUNK) {
        int t = 0;
        #pragma unroll
        for (int k = 0; k < NCHUNK / 32; k++) t += swsum[k];
        s_total = (t < SS) ? t : SS;
    }
    __syncthreads();

    // ---- P7: store (tail implicitly zero) --------------------------------
    {
        const int total = s_total;                      // valid range [0, total)
        float4* o4 = (float4*)(out + base);
        const float4* s4 = (const float4*)outrow;
        #pragma unroll
        for (int i = tid; i < SS / 4; i += NT) {
            int e0 = i * 4;
            float4 v;
            if (e0 + 3 < total) {
                v = s4[i];
            } else if (e0 >= total) {
                v = make_float4(0.0f, 0.0f, 0.0f, 0.0f);
            } else {
                v.x = (e0     < total) ? outrow[e0]     : 0.0f;
                v.y = (e0 + 1 < total) ? outrow[e0 + 1] : 0.0f;
                v.z = (e0 + 2 < total) ? outrow[e0 + 2] : 0.0f;
                v.w = (e0 + 3 < total) ? outrow[e0 + 3] : 0.0f;
            }
            o4[i] = v;
        }
    }
}

extern "C" void kernel_launch(void* const* d_in, const int* in_sizes, int n_in,
                              void* d_out, int out_size)
{
    const float* x   = (const float*)d_in[0];
    const float* dly = (const float*)d_in[1];
    const float* rtt = (const float*)d_in[2];
    float* out = (float*)d_out;

    int B = in_sizes[0] / SS;
    p1_kernel<<<B, NT>>>(x, dly, rtt);
    p2_kernel<<<B, NT>>>(x, out);
}

// round 16
// speedup vs baseline: 1.4559x; 1.4559x over previous
#include <cuda_runtime.h>
#include <cuda_bf16.h>

// TrafficAugmentation [B=2048, S=4096] -> [B, S, 1] f32.
//
// Two kernels:
//  K1 (P1): lean per-position delay countdown (branchless paired walks,
//      aligned LDS.128, deferred crossing resolve) -> g_snxt (u16).
//      Only dly staged in SMEM (16.4KB).
//  K2 (P2-P7): stages x + snxt; CHUNK=16 so ALL 256 threads own a chunk
//      in P4/P6 (was 128 idle at CHUNK=32). Exit table via 4-step shfl
//      pointer doubling (16-wide chunks inside 32-lane groups), serial
//      top walk over 256 chunks (branchy skip), per-chunk counts with
//      cached (nf,rem), 256-wide scan, dense emission, tail-zero store.
//      outrow aliases dead sx.

#define SS     4096
#define CHUNK  16
#define NCHUNK (SS / CHUNK)     // 256 == NT
#define MSSF   1448.0f
#define KILL16 0x8000u
#define NT     256
#define BMAX   2048

__device__ unsigned short g_snxt[(size_t)BMAX * SS];   // 16MB scratch

// Exact index-ordered sum of sx[s0..e1) via aligned float4 LDS loads;
// fp op order identical to the scalar loop (predicated edges).
__device__ __forceinline__ float burst_sum(const float* __restrict__ sxp,
                                           int s0, int e1)
{
    const float4* v4 = (const float4*)sxp;
    float buf = 0.0f;
    for (int jb = (s0 & ~3); jb < e1; jb += 4) {
        float4 v = v4[jb >> 2];
        if (jb     >= s0)                 buf = __fadd_rn(buf, v.x);
        if (jb + 1 >= s0 && jb + 1 < e1)  buf = __fadd_rn(buf, v.y);
        if (jb + 2 >= s0 && jb + 2 < e1)  buf = __fadd_rn(buf, v.z);
        if (jb + 3 >= s0 && jb + 3 < e1)  buf = __fadd_rn(buf, v.w);
    }
    return buf;
}

// ======================= K1: burst-end computation =======================
__global__ __launch_bounds__(NT)
void p1_kernel(const float* __restrict__ x,
               const float* __restrict__ dly,
               const float* __restrict__ rtt)
{
    __shared__ __align__(16) float sd[SS + 4];   // dly row + 1e30 pads

    const int row  = blockIdx.x;
    const size_t base = (size_t)row * SS;
    const int tid = threadIdx.x;

    {
        const float4* d4 = (const float4*)(dly + base);
        float4* sd4w = (float4*)sd;
        #pragma unroll
        for (int i = tid; i < SS / 4; i += NT) sd4w[i] = d4[i];
        if (tid < 4) sd[SS + tid] = 1e30f;
    }
    __syncthreads();

    const float4* sd4 = (const float4*)sd;
    const int phase = tid & 3;                   // s mod 4, constant over k
    unsigned short* snr = g_snxt + base;

    #pragma unroll 1
    for (int k = 0; k < SS / NT; k += 2) {
        const int sA = tid + k * NT;
        const int sB = sA + NT;
        float rA = __ldg(rtt + base + sA);       // issue early (MLP)
        float rB = __ldg(rtt + base + sB);
        const bool aliveA = (__ldg(x + base + sA) > 0.0f);
        const bool aliveB = (__ldg(x + base + sB) > 0.0f);
        int jA = sA - phase, jB = sB - phase;    // aligned batch starts
        int doneA = !aliveA, doneB = !aliveB;

        // peel: first batch with masked prefix (fsub(r,0) == identity)
        {
            float4 va = sd4[jA >> 2];
            float4 vb = sd4[jB >> 2];
            float a0 = (phase == 0) ? va.x : 0.0f;
            float a1 = (phase <= 1) ? va.y : 0.0f;
            float a2 = (phase <= 2) ? va.z : 0.0f;
            float b0 = (phase == 0) ? vb.x : 0.0f;
            float b1 = (phase <= 1) ? vb.y : 0.0f;
            float b2 = (phase <= 2) ? vb.z : 0.0f;
            float A4 = __fsub_rn(__fsub_rn(__fsub_rn(
                           __fsub_rn(rA, a0), a1), a2), va.w);
            float B4 = __fsub_rn(__fsub_rn(__fsub_rn(
                           __fsub_rn(rB, b0), b1), b2), vb.w);
            const int frzA = doneA | (A4 <= 0.0f);
            const int frzB = doneB | (B4 <= 0.0f);
            jA = frzA ? jA : jA + 4;             // freeze at terminal batch
            jB = frzB ? jB : jB + 4;
            rA = frzA ? rA : A4;                 // freeze batch-entry r
            rB = frzB ? rB : B4;
            doneA = frzA;
            doneB = frzB;
        }

        // steady state: aligned, unmasked; frozen walks replay idempotently
        while (!(doneA & doneB)) {
            float4 va = sd4[jA >> 2];
            float4 vb = sd4[jB >> 2];
            float A4 = __fsub_rn(__fsub_rn(__fsub_rn(
                           __fsub_rn(rA, va.x), va.y), va.z), va.w);
            float B4 = __fsub_rn(__fsub_rn(__fsub_rn(
                           __fsub_rn(rB, vb.x), vb.y), vb.z), vb.w);
            const int frzA = doneA | (A4 <= 0.0f);
            const int frzB = doneB | (B4 <= 0.0f);
            jA = frzA ? jA : jA + 4;
            jB = frzB ? jB : jB + 4;
            rA = frzA ? rA : A4;
            rB = frzB ? rB : B4;
            doneA = frzA;
            doneB = frzB;
            // 1e30 pads at sd[SS..SS+3] force termination just past SS
        }

        // resolve crossing once per walk (bit-exact replay of terminal batch)
        {
            float4 va = sd4[jA >> 2];
            float d0 = (jA     >= sA) ? va.x : 0.0f;
            float d1 = (jA + 1 >= sA) ? va.y : 0.0f;
            float d2 = (jA + 2 >= sA) ? va.z : 0.0f;
            float A1 = __fsub_rn(rA, d0);
            float A2 = __fsub_rn(A1, d1);
            float A3 = __fsub_rn(A2, d2);
            int c = jA + 1 + (int)(A1 > 0.0f) + (int)(A2 > 0.0f)
                           + (int)(A3 > 0.0f);
            c = (c > sA + 1) ? c : sA + 1;       // r<=0 at start: consume 1
            c = (c < SS) ? c : SS;
            snr[sA] = aliveA ? (unsigned short)c : (unsigned short)KILL16;
        }
        {
            float4 vb = sd4[jB >> 2];
            float d0 = (jB     >= sB) ? vb.x : 0.0f;
            float d1 = (jB + 1 >= sB) ? vb.y : 0.0f;
            float d2 = (jB + 2 >= sB) ? vb.z : 0.0f;
            float B1 = __fsub_rn(rB, d0);
            float B2 = __fsub_rn(B1, d1);
            float B3 = __fsub_rn(B2, d2);
            int c = jB + 1 + (int)(B1 > 0.0f) + (int)(B2 > 0.0f)
                           + (int)(B3 > 0.0f);
            c = (c > sB + 1) ? c : sB + 1;
            c = (c < SS) ? c : SS;
            snr[sB] = aliveB ? (unsigned short)c : (unsigned short)KILL16;
        }
    }
}

// ======================= K2: chain walk + emission =======================
__global__ __launch_bounds__(NT)
void p2_kernel(const float* __restrict__ x,
               float* __restrict__ out)
{
    __shared__ __align__(16) float sx[SS + 4];   // x row + 0 pads; P6/P7: outrow
    __shared__ unsigned short ssnxt[SS];         // burst-end | kill
    __shared__ unsigned short sexit[SS];         // chunk-exit table
    __shared__ unsigned short senter[NCHUNK];    // chain entry per chunk (256)
    __shared__ int swsum[NT / 32];               // per-warp count totals
    __shared__ int s_total;                      // grand output count

    const int row  = blockIdx.x;
    const size_t base = (size_t)row * SS;
    const int tid = threadIdx.x;

    // ---- P0: stage x + snxt row ------------------------------------------
    {
        const float4* x4 = (const float4*)(x + base);
        float4* sx4 = (float4*)sx;
        const uint4* n4 = (const uint4*)(g_snxt + base);
        uint4* sn4 = (uint4*)ssnxt;
        #pragma unroll
        for (int i = tid; i < SS / 4; i += NT) sx4[i] = x4[i];
        #pragma unroll
        for (int i = tid; i < SS / 8; i += NT) sn4[i] = n4[i];
        if (tid < 4) sx[SS + tid] = 0.0f;
    }
    __syncthreads();

    // ---- P2: exit table via shfl pointer doubling (16-wide chunks) -------
    {
        const int wid  = tid >> 5;
        const int lane = tid & 31;
        for (int g = wid; g < SS / 32; g += NT / 32) { // 32-pos groups
            const int gbase = g * 32;
            // this lane's chunk end: first or second 16-wide half
            const int cend = gbase + ((lane & 16) ? 32 : 16);
            unsigned short w = ssnxt[gbase + lane];
            int E = (w & KILL16) ? SS : (int)w;        // kill -> chain dies
            #pragma unroll
            for (int step = 0; step < 4; step++) {     // 2^4 >= CHUNK(16)
                int val = __shfl_sync(0xffffffffu, E, E & 31);
                E = (E < cend) ? val : E;              // jumps stay in-chunk
            }
            sexit[gbase + lane] = (unsigned short)E;
        }
    }
    __syncthreads();

    // ---- P3: serial top walk (<= NCHUNK hops, branchy skip) --------------
    if (tid == 0) {
        int pos = 0;
        #pragma unroll 4
        for (int c = 0; c < NCHUNK; c++) {
            senter[c] = (unsigned short)pos;
            if (pos < (c + 1) * CHUNK) pos = sexit[pos];
        }
    }
    __syncthreads();

    // ---- P4: per-chunk counts (ALL 256 threads) + (nf, rem) cache --------
    unsigned long long lburst[CHUNK];            // <=16 bursts per 16-chunk
    int cnt = 0, nb = 0;
    {
        const int end = (tid + 1) * CHUNK;
        int s = senter[tid];
        while (s < end) {
            unsigned short w = ssnxt[s];
            if (w & KILL16) break;
            const int e1 = (int)w;
            float buf = burst_sum(sx, s, e1);         // exact index order
            int nf = (int)ceilf(__fdiv_rn(buf, MSSF)) - 1;
            if (nf < 0) nf = 0;
            float rem = __fsub_rn(buf, __fmul_rn((float)nf, MSSF));
            cnt += nf + (rem > 0.0f ? 1 : 0);
            lburst[nb++] = ((unsigned long long)__float_as_uint(rem) << 32)
                         | (unsigned int)nf;
            s = e1;
        }
    }
    __syncthreads();   // sx dead after this point -> becomes outrow

    // ---- P5: block-wide exclusive scan of chunk counts -------------------
    int inc = cnt;
    {
        const int lane = tid & 31;
        #pragma unroll
        for (int d = 1; d < 32; d <<= 1) {
            int n = __shfl_up_sync(0xffffffffu, inc, d);
            if (lane >= d) inc += n;
        }
        if (lane == 31) swsum[tid >> 5] = inc;          // warp inclusive total
    }
    __syncthreads();

    // ---- P6: dense emission of cached bursts + grand total ---------------
    float* outrow = sx;
    {
        int o = inc - cnt;                              // exclusive within warp
        #pragma unroll
        for (int k = 0; k < NT / 32; k++)
            if (k < (tid >> 5)) o += swsum[k];
        if (tid == NT - 1) {                            // last chunk: total
            int t = o + cnt;
            s_total = (t < SS) ? t : SS;
        }
        for (int i = 0; i < nb; i++) {
            unsigned long long v = lburst[i];
            int nf    = (int)(unsigned int)(v & 0xFFFFFFFFu);
            float rem = __uint_as_float((unsigned int)(v >> 32));
            int lim = nf;
            if (o + lim > SS) lim = SS - o;             // truncation (may be <=0)
            for (int k = 0; k < lim; k++) outrow[o + k] = MSSF;
            if (rem > 0.0f && o + nf < SS) outrow[o + nf] = rem;
            o += nf + (rem > 0.0f ? 1 : 0);             // slots [o,o+cnt) dense
        }
    }
    __syncthreads();

    // ---- P7: store (tail implicitly zero) --------------------------------
    {
        const int total = s_total;                      // valid range [0, total)
        float4* o4 = (float4*)(out + base);
        const float4* s4 = (const float4*)outrow;
        #pragma unroll
        for (int i = tid; i < SS / 4; i += NT) {
            int e0 = i * 4;
            float4 v;
            if (e0 + 3 < total) {
                v = s4[i];
            } else if (e0 >= total) {
                v = make_float4(0.0f, 0.0f, 0.0f, 0.0f);
            } else {
                v.x = (e0     < total) ? outrow[e0]     : 0.0f;
                v.y = (e0 + 1 < total) ? outrow[e0 + 1] : 0.0f;
                v.z = (e0 + 2 < total) ? outrow[e0 + 2] : 0.0f;
                v.w = (e0 + 3 < total) ? outrow[e0 + 3] : 0.0f;
            }
            o4[i] = v;
        }
    }
}

extern "C" void kernel_launch(void* const* d_in, const int* in_sizes, int n_in,
                              void* d_out, int out_size)
{
    const float* x   = (const float*)d_in[0];
    const float* dly = (const float*)d_in[1];
    const float* rtt = (const float*)d_in[2];
    float* out = (float*)d_out;

    int B = in_sizes[0] / SS;
    p1_kernel<<<B, NT>>>(x, dly, rtt);
    p2_kernel<<<B, NT>>>(x, out);
}

// round 17
// speedup vs baseline: 1.5172x; 1.0421x over previous
#include <cuda_runtime.h>
#include <cuda_bf16.h>

// TrafficAugmentation [B=2048, S=4096] -> [B, S, 1] f32.
//
// Two kernels:
//  K1 (P1): lean per-position delay countdown (branchless paired walks,
//      aligned LDS.128, deferred crossing resolve) -> g_snxt (u16).
//  K2 (P2-P7): stages x + snxt; CHUNK=16 (all 256 threads own a chunk).
//      Emission is divergence-free: outrow is filled with MSS uniformly,
//      then ONLY per-burst remainders are scattered (slots [o,o+nf) are
//      always MSS and bursts tile [0,total) densely); the zero tail is
//      masked in the store by total. outrow aliases dead sx.

#define SS     4096
#define CHUNK  16
#define NCHUNK (SS / CHUNK)     // 256 == NT
#define MSSF   1448.0f
#define KILL16 0x8000u
#define NT     256
#define BMAX   2048

__device__ unsigned short g_snxt[(size_t)BMAX * SS];   // 16MB scratch

// Exact index-ordered sum of sx[s0..e1) via aligned float4 LDS loads;
// fp op order identical to the scalar loop (predicated edges).
__device__ __forceinline__ float burst_sum(const float* __restrict__ sxp,
                                           int s0, int e1)
{
    const float4* v4 = (const float4*)sxp;
    float buf = 0.0f;
    for (int jb = (s0 & ~3); jb < e1; jb += 4) {
        float4 v = v4[jb >> 2];
        if (jb     >= s0)                 buf = __fadd_rn(buf, v.x);
        if (jb + 1 >= s0 && jb + 1 < e1)  buf = __fadd_rn(buf, v.y);
        if (jb + 2 >= s0 && jb + 2 < e1)  buf = __fadd_rn(buf, v.z);
        if (jb + 3 >= s0 && jb + 3 < e1)  buf = __fadd_rn(buf, v.w);
    }
    return buf;
}

// ======================= K1: burst-end computation =======================
__global__ __launch_bounds__(NT)
void p1_kernel(const float* __restrict__ x,
               const float* __restrict__ dly,
               const float* __restrict__ rtt)
{
    __shared__ __align__(16) float sd[SS + 4];   // dly row + 1e30 pads

    const int row  = blockIdx.x;
    const size_t base = (size_t)row * SS;
    const int tid = threadIdx.x;

    {
        const float4* d4 = (const float4*)(dly + base);
        float4* sd4w = (float4*)sd;
        #pragma unroll
        for (int i = tid; i < SS / 4; i += NT) sd4w[i] = d4[i];
        if (tid < 4) sd[SS + tid] = 1e30f;
    }
    __syncthreads();

    const float4* sd4 = (const float4*)sd;
    const int phase = tid & 3;                   // s mod 4, constant over k
    unsigned short* snr = g_snxt + base;

    #pragma unroll 1
    for (int k = 0; k < SS / NT; k += 2) {
        const int sA = tid + k * NT;
        const int sB = sA + NT;
        float rA = __ldg(rtt + base + sA);       // issue early (MLP)
        float rB = __ldg(rtt + base + sB);
        const bool aliveA = (__ldg(x + base + sA) > 0.0f);
        const bool aliveB = (__ldg(x + base + sB) > 0.0f);
        int jA = sA - phase, jB = sB - phase;    // aligned batch starts
        int doneA = !aliveA, doneB = !aliveB;

        // peel: first batch with masked prefix (fsub(r,0) == identity)
        {
            float4 va = sd4[jA >> 2];
            float4 vb = sd4[jB >> 2];
            float a0 = (phase == 0) ? va.x : 0.0f;
            float a1 = (phase <= 1) ? va.y : 0.0f;
            float a2 = (phase <= 2) ? va.z : 0.0f;
            float b0 = (phase == 0) ? vb.x : 0.0f;
            float b1 = (phase <= 1) ? vb.y : 0.0f;
            float b2 = (phase <= 2) ? vb.z : 0.0f;
            float A4 = __fsub_rn(__fsub_rn(__fsub_rn(
                           __fsub_rn(rA, a0), a1), a2), va.w);
            float B4 = __fsub_rn(__fsub_rn(__fsub_rn(
                           __fsub_rn(rB, b0), b1), b2), vb.w);
            const int frzA = doneA | (A4 <= 0.0f);
            const int frzB = doneB | (B4 <= 0.0f);
            jA = frzA ? jA : jA + 4;             // freeze at terminal batch
            jB = frzB ? jB : jB + 4;
            rA = frzA ? rA : A4;                 // freeze batch-entry r
            rB = frzB ? rB : B4;
            doneA = frzA;
            doneB = frzB;
        }

        // steady state: aligned, unmasked; frozen walks replay idempotently
        while (!(doneA & doneB)) {
            float4 va = sd4[jA >> 2];
            float4 vb = sd4[jB >> 2];
            float A4 = __fsub_rn(__fsub_rn(__fsub_rn(
                           __fsub_rn(rA, va.x), va.y), va.z), va.w);
            float B4 = __fsub_rn(__fsub_rn(__fsub_rn(
                           __fsub_rn(rB, vb.x), vb.y), vb.z), vb.w);
            const int frzA = doneA | (A4 <= 0.0f);
            const int frzB = doneB | (B4 <= 0.0f);
            jA = frzA ? jA : jA + 4;
            jB = frzB ? jB : jB + 4;
            rA = frzA ? rA : A4;
            rB = frzB ? rB : B4;
            doneA = frzA;
            doneB = frzB;
            // 1e30 pads at sd[SS..SS+3] force termination just past SS
        }

        // resolve crossing once per walk (bit-exact replay of terminal batch)
        {
            float4 va = sd4[jA >> 2];
            float d0 = (jA     >= sA) ? va.x : 0.0f;
            float d1 = (jA + 1 >= sA) ? va.y : 0.0f;
            float d2 = (jA + 2 >= sA) ? va.z : 0.0f;
            float A1 = __fsub_rn(rA, d0);
            float A2 = __fsub_rn(A1, d1);
            float A3 = __fsub_rn(A2, d2);
            int c = jA + 1 + (int)(A1 > 0.0f) + (int)(A2 > 0.0f)
                           + (int)(A3 > 0.0f);
            c = (c > sA + 1) ? c : sA + 1;       // r<=0 at start: consume 1
            c = (c < SS) ? c : SS;
            snr[sA] = aliveA ? (unsigned short)c : (unsigned short)KILL16;
        }
        {
            float4 vb = sd4[jB >> 2];
            float d0 = (jB     >= sB) ? vb.x : 0.0f;
            float d1 = (jB + 1 >= sB) ? vb.y : 0.0f;
            float d2 = (jB + 2 >= sB) ? vb.z : 0.0f;
            float B1 = __fsub_rn(rB, d0);
            float B2 = __fsub_rn(B1, d1);
            float B3 = __fsub_rn(B2, d2);
            int c = jB + 1 + (int)(B1 > 0.0f) + (int)(B2 > 0.0f)
                           + (int)(B3 > 0.0f);
            c = (c > sB + 1) ? c : sB + 1;
            c = (c < SS) ? c : SS;
            snr[sB] = aliveB ? (unsigned short)c : (unsigned short)KILL16;
        }
    }
}

// ======================= K2: chain walk + emission =======================
__global__ __launch_bounds__(NT)
void p2_kernel(const float* __restrict__ x,
               float* __restrict__ out)
{
    __shared__ __align__(16) float sx[SS + 4];   // x row + 0 pads; later outrow
    __shared__ unsigned short ssnxt[SS];         // burst-end | kill
    __shared__ unsigned short sexit[SS];         // chunk-exit table
    __shared__ unsigned short senter[NCHUNK];    // chain entry per chunk (256)
    __shared__ int swsum[NT / 32];               // per-warp count totals
    __shared__ int s_total;                      // grand output count

    const int row  = blockIdx.x;
    const size_t base = (size_t)row * SS;
    const int tid = threadIdx.x;

    // ---- P0: stage x + snxt row ------------------------------------------
    {
        const float4* x4 = (const float4*)(x + base);
        float4* sx4 = (float4*)sx;
        const uint4* n4 = (const uint4*)(g_snxt + base);
        uint4* sn4 = (uint4*)ssnxt;
        #pragma unroll
        for (int i = tid; i < SS / 4; i += NT) sx4[i] = x4[i];
        #pragma unroll
        for (int i = tid; i < SS / 8; i += NT) sn4[i] = n4[i];
        if (tid < 4) sx[SS + tid] = 0.0f;
    }
    __syncthreads();

    // ---- P2: exit table via shfl pointer doubling (16-wide chunks) -------
    {
        const int wid  = tid >> 5;
        const int lane = tid & 31;
        for (int g = wid; g < SS / 32; g += NT / 32) { // 32-pos groups
            const int gbase = g * 32;
            const int cend = gbase + ((lane & 16) ? 32 : 16);
            unsigned short w = ssnxt[gbase + lane];
            int E = (w & KILL16) ? SS : (int)w;        // kill -> chain dies
            #pragma unroll
            for (int step = 0; step < 4; step++) {     // 2^4 >= CHUNK(16)
                int val = __shfl_sync(0xffffffffu, E, E & 31);
                E = (E < cend) ? val : E;              // jumps stay in-chunk
            }
            sexit[gbase + lane] = (unsigned short)E;
        }
    }
    __syncthreads();

    // ---- P3: serial top walk (<= NCHUNK hops, branchy skip) --------------
    if (tid == 0) {
        int pos = 0;
        #pragma unroll 4
        for (int c = 0; c < NCHUNK; c++) {
            senter[c] = (unsigned short)pos;
            if (pos < (c + 1) * CHUNK) pos = sexit[pos];
        }
    }
    __syncthreads();

    // ---- P4: per-chunk counts (all 256 threads) + (nf, rem) cache --------
    unsigned long long lburst[CHUNK];            // <=16 bursts per 16-chunk
    int cnt = 0, nb = 0;
    {
        const int end = (tid + 1) * CHUNK;
        int s = senter[tid];
        while (s < end) {
            unsigned short w = ssnxt[s];
            if (w & KILL16) break;
            const int e1 = (int)w;
            float buf = burst_sum(sx, s, e1);         // exact index order
            int nf = (int)ceilf(__fdiv_rn(buf, MSSF)) - 1;
            if (nf < 0) nf = 0;
            float rem = __fsub_rn(buf, __fmul_rn((float)nf, MSSF));
            cnt += nf + (rem > 0.0f ? 1 : 0);
            lburst[nb++] = ((unsigned long long)__float_as_uint(rem) << 32)
                         | (unsigned int)nf;
            s = e1;
        }
    }
    __syncthreads();   // sx dead after this point -> becomes outrow

    // ---- P5: block scan of chunk counts + uniform MSS fill ---------------
    float* outrow = sx;
    int inc = cnt;
    {
        const int lane = tid & 31;
        #pragma unroll
        for (int d = 1; d < 32; d <<= 1) {
            int n = __shfl_up_sync(0xffffffffu, inc, d);
            if (lane >= d) inc += n;
        }
        if (lane == 31) swsum[tid >> 5] = inc;          // warp inclusive total
        // uniform fill: every slot MSS (tail masked by total in P7,
        // remainder slots overwritten in P6)
        float4* o4f = (float4*)outrow;
        const float4 m4 = make_float4(MSSF, MSSF, MSSF, MSSF);
        #pragma unroll
        for (int i = tid; i < SS / 4; i += NT) o4f[i] = m4;
    }
    __syncthreads();

    // ---- P6: remainder-only scatter + grand total ------------------------
    {
        int o = inc - cnt;                              // exclusive within warp
        #pragma unroll
        for (int k = 0; k < NT / 32; k++)
            if (k < (tid >> 5)) o += swsum[k];
        if (tid == NT - 1) {                            // last chunk: total
            int t = o + cnt;
            s_total = (t < SS) ? t : SS;
        }
        for (int i = 0; i < nb; i++) {
            unsigned long long v = lburst[i];
            int nf    = (int)(unsigned int)(v & 0xFFFFFFFFu);
            float rem = __uint_as_float((unsigned int)(v >> 32));
            int rp = o + nf;                            // remainder slot
            if (rem > 0.0f && rp < SS) outrow[rp] = rem;
            o += nf + (rem > 0.0f ? 1 : 0);             // slots [o,o+cnt) dense
        }
    }
    __syncthreads();

    // ---- P7: store (tail zeroed via total) -------------------------------
    {
        const int total = s_total;                      // valid range [0, total)
        float4* o4 = (float4*)(out + base);
        const float4* s4 = (const float4*)outrow;
        #pragma unroll
        for (int i = tid; i < SS / 4; i += NT) {
            int e0 = i * 4;
            float4 v;
            if (e0 + 3 < total) {
                v = s4[i];
            } else if (e0 >= total) {
                v = make_float4(0.0f, 0.0f, 0.0f, 0.0f);
            } else {
                v.x = (e0     < total) ? outrow[e0]     : 0.0f;
                v.y = (e0 + 1 < total) ? outrow[e0 + 1] : 0.0f;
                v.z = (e0 + 2 < total) ? outrow[e0 + 2] : 0.0f;
                v.w = (e0 + 3 < total) ? outrow[e0 + 3] : 0.0f;
            }
            o4[i] = v;
        }
    }
}

extern "C" void kernel_launch(void* const* d_in, const int* in_sizes, int n_in,
                              void* d_out, int out_size)
{
    const float* x   = (const float*)d_in[0];
    const float* dly = (const float*)d_in[1];
    const float* rtt = (const float*)d_in[2];
    float* out = (float*)d_out;

    int B = in_sizes[0] / SS;
    p1_kernel<<<B, NT>>>(x, dly, rtt);
    p2_kernel<<<B, NT>>>(x, out);
}